// round 4
// baseline (speedup 1.0000x reference)
#include <cuda_runtime.h>

// Problem constants
#define N_   8
#define C_   256
#define H_   128
#define W_   128
#define HW_  16384
#define NB_  20
#define TEMP 0.5f
#define IMGW 800.0f
#define IMGH 800.0f

#define K1_CHUNKS 64                 // hw chunks per image in K1
#define K1_BLOCKS (N_ * K1_CHUNKS)   // 512
#define K6_BLOCKS 1024

// Scratch (no allocation allowed -> __device__ globals)
__device__ float g_rowsum[N_ * HW_];          // sum_c |T|, indexed [n*HW + hw]
__device__ float g_colpart[K1_BLOCKS * C_];   // per-block partial channel sums
__device__ float g_sqC[N_ * C_];              // sqrt(C_att)
__device__ float g_smax[N_], g_ssum[N_];      // spatial softmax stats
__device__ float g_fg[N_ * HW_];              // fg mask, [n*HW + hw]
__device__ float g_bgcnt[N_];                 // bg cell counts
__device__ float g_roww[N_ * HW_];            // per-row weight, indexed r = hw*N + n
__device__ float g_part[K6_BLOCKS];           // main-pass block partials

// ---------------------------------------------------------------------------
// K1: one pass over preds_T. Row sums of |T| + partial channel sums.
// Grid: (K1_CHUNKS, N_), 256 threads (8 warps). Warp handles rows strided by 8.
// ---------------------------------------------------------------------------
__global__ void __launch_bounds__(256) k1_stats(const float* __restrict__ T) {
    const int n = blockIdx.y;
    const int chunk = blockIdx.x;
    const int w = threadIdx.x >> 5;
    const int l = threadIdx.x & 31;

    __shared__ float scol[8][C_];

    float col[8];
#pragma unroll
    for (int j = 0; j < 8; j++) col[j] = 0.0f;

    const int hw0 = chunk * (HW_ / K1_CHUNKS);   // 256 rows per block
#pragma unroll 4
    for (int i = 0; i < 32; i++) {
        const int hw = hw0 + w + 8 * i;
        const float4* p = reinterpret_cast<const float4*>(T + (size_t)(hw * N_ + n) * C_);
        float4 a = p[l];        // c = 4l .. 4l+3
        float4 b = p[32 + l];   // c = 128+4l ..
        float a0 = fabsf(a.x), a1 = fabsf(a.y), a2 = fabsf(a.z), a3 = fabsf(a.w);
        float b0 = fabsf(b.x), b1 = fabsf(b.y), b2 = fabsf(b.z), b3 = fabsf(b.w);
        col[0] += a0; col[1] += a1; col[2] += a2; col[3] += a3;
        col[4] += b0; col[5] += b1; col[6] += b2; col[7] += b3;
        float rs = (a0 + a1) + (a2 + a3) + (b0 + b1) + (b2 + b3);
#pragma unroll
        for (int off = 16; off; off >>= 1)
            rs += __shfl_xor_sync(0xffffffffu, rs, off);
        if (l == 0) g_rowsum[n * HW_ + hw] = rs;
    }

#pragma unroll
    for (int j = 0; j < 4; j++) {
        scol[w][4 * l + j]       = col[j];
        scol[w][128 + 4 * l + j] = col[4 + j];
    }
    __syncthreads();

    const int t = threadIdx.x;  // 256 threads == C_
    float p = 0.0f;
#pragma unroll
    for (int ww = 0; ww < 8; ww++) p += scol[ww][t];
    g_colpart[(n * K1_CHUNKS + chunk) * C_ + t] = p;
}

// ---------------------------------------------------------------------------
// K2: channel softmax -> sqrt(C * softmax(colsum/HW/TEMP)). Grid: N_, 256 thr.
// ---------------------------------------------------------------------------
__global__ void __launch_bounds__(256) k2_channel() {
    const int n = blockIdx.x;
    const int c = threadIdx.x;
    float v = 0.0f;
    for (int k = 0; k < K1_CHUNKS; k++)
        v += g_colpart[(n * K1_CHUNKS + k) * C_ + c];
    const float logit = (v / (float)HW_) / TEMP;

    __shared__ float sh[256];
    sh[c] = logit;
    __syncthreads();
    for (int s = 128; s; s >>= 1) {
        if (c < s) sh[c] = fmaxf(sh[c], sh[c + s]);
        __syncthreads();
    }
    const float mx = sh[0];
    __syncthreads();

    const float e = expf(logit - mx);
    sh[c] = e;
    __syncthreads();
    for (int s = 128; s; s >>= 1) {
        if (c < s) sh[c] += sh[c + s];
        __syncthreads();
    }
    const float sum = sh[0];
    g_sqC[n * C_ + c] = sqrtf((float)C_ * e / sum);
}

// ---------------------------------------------------------------------------
// K3: spatial softmax stats (max, sum of exp) per image. Grid: N_, 256 thr.
// ---------------------------------------------------------------------------
__global__ void __launch_bounds__(256) k3_spatial() {
    const int n = blockIdx.x;
    const int t = threadIdx.x;
    __shared__ float sh[256];

    float mx = -1e30f;
    for (int i = t; i < HW_; i += 256) {
        float lg = (g_rowsum[n * HW_ + i] / (float)C_) / TEMP;
        mx = fmaxf(mx, lg);
    }
    sh[t] = mx;
    __syncthreads();
    for (int s = 128; s; s >>= 1) {
        if (t < s) sh[t] = fmaxf(sh[t], sh[t + s]);
        __syncthreads();
    }
    mx = sh[0];
    __syncthreads();

    float sum = 0.0f;
    for (int i = t; i < HW_; i += 256)
        sum += expf((g_rowsum[n * HW_ + i] / (float)C_) / TEMP - mx);
    sh[t] = sum;
    __syncthreads();
    for (int s = 128; s; s >>= 1) {
        if (t < s) sh[t] += sh[t + s];
        __syncthreads();
    }
    if (t == 0) { g_smax[n] = mx; g_ssum[n] = sh[0]; }
}

// ---------------------------------------------------------------------------
// K4: box masks. fg map + bg cell count per image. Grid: N_, 256 thr.
// ---------------------------------------------------------------------------
__global__ void __launch_bounds__(256) k4_mask(const float* __restrict__ gt) {
    const int n = blockIdx.x;
    const int t = threadIdx.x;

    __shared__ int   shmin[NB_], shmax[NB_], swmin[NB_], swmax[NB_];
    __shared__ float sarea[NB_];
    if (t < NB_) {
        const float* b = gt + (size_t)(n * NB_ + t) * 4;
        int wmin = (int)floorf(b[0] / IMGW * (float)W_);
        int wmax = (int)ceilf (b[2] / IMGW * (float)W_);
        int hmin = (int)floorf(b[1] / IMGH * (float)H_);
        int hmax = (int)ceilf (b[3] / IMGH * (float)H_);
        swmin[t] = wmin; swmax[t] = wmax; shmin[t] = hmin; shmax[t] = hmax;
        sarea[t] = 1.0f / (float)(hmax + 1 - hmin) / (float)(wmax + 1 - wmin);
    }
    __syncthreads();

    int cnt = 0;
    for (int i = t; i < HW_; i += 256) {
        const int hh = i / W_;
        const int ww = i % W_;
        float fg = 0.0f;
#pragma unroll
        for (int b = 0; b < NB_; b++) {
            bool inside = (hh >= shmin[b]) & (hh <= shmax[b]) &
                          (ww >= swmin[b]) & (ww <= swmax[b]);
            if (inside) fg = fmaxf(fg, sarea[b]);
        }
        g_fg[n * HW_ + i] = fg;
        if (fg <= 0.0f) cnt++;
    }
    __shared__ int sh[256];
    sh[t] = cnt;
    __syncthreads();
    for (int s = 128; s; s >>= 1) {
        if (t < s) sh[t] += sh[t + s];
        __syncthreads();
    }
    if (t == 0) g_bgcnt[n] = (float)sh[0];
}

// ---------------------------------------------------------------------------
// K5: per-row weight w_row = sqrt(S_att) * (sqrt(fg) + sqrt(bg)).
// Output indexed by memory order r = hw*N + n. Grid: N_*HW_/256 blocks.
// ---------------------------------------------------------------------------
__global__ void __launch_bounds__(256) k5_roww() {
    const int r = blockIdx.x * 256 + threadIdx.x;   // r = hw*N + n
    const int n  = r & (N_ - 1);
    const int hw = r >> 3;
    const float rs = g_rowsum[n * HW_ + hw];
    const float satt = (float)HW_ * expf((rs / (float)C_) / TEMP - g_smax[n]) / g_ssum[n];
    const float fg = g_fg[n * HW_ + hw];
    const float cnt = g_bgcnt[n];
    const float bg = (fg <= 0.0f) ? ((cnt > 0.0f) ? 1.0f / cnt : 1.0f) : 0.0f;
    g_roww[r] = sqrtf(satt) * (sqrtf(fg) + sqrtf(bg));
}

// ---------------------------------------------------------------------------
// K6: main pass over S and T. Warp per row (1 KB contiguous), deterministic
// block partials. Grid: K6_BLOCKS, 256 thr (8 warps).
// ---------------------------------------------------------------------------
__global__ void __launch_bounds__(256) k6_main(const float* __restrict__ S,
                                              const float* __restrict__ T) {
    __shared__ float sqc[N_ * C_];
    for (int i = threadIdx.x; i < N_ * C_; i += 256) sqc[i] = g_sqC[i];
    __syncthreads();

    const int w = threadIdx.x >> 5;
    const int l = threadIdx.x & 31;
    const int gw = blockIdx.x * 8 + w;
    const int NW = K6_BLOCKS * 8;

    float acc = 0.0f;
    for (int r = gw; r < N_ * HW_; r += NW) {
        const int n = r & (N_ - 1);
        const float4* ps = reinterpret_cast<const float4*>(S + (size_t)r * C_);
        const float4* pt = reinterpret_cast<const float4*>(T + (size_t)r * C_);
        float4 a = ps[l],      b = pt[l];
        float4 c = ps[32 + l], d = pt[32 + l];
        const float4* qr = reinterpret_cast<const float4*>(sqc + n * C_);
        float4 qa = qr[l], qb = qr[32 + l];

        float v = fabsf(a.x - b.x) * qa.x + fabsf(a.y - b.y) * qa.y
                + fabsf(a.z - b.z) * qa.z + fabsf(a.w - b.w) * qa.w
                + fabsf(c.x - d.x) * qb.x + fabsf(c.y - d.y) * qb.y
                + fabsf(c.z - d.z) * qb.z + fabsf(c.w - d.w) * qb.w;
#pragma unroll
        for (int off = 16; off; off >>= 1)
            v += __shfl_xor_sync(0xffffffffu, v, off);
        acc += v * g_roww[r];
    }

    __shared__ float sp[8];
    if (l == 0) sp[w] = acc;
    __syncthreads();
    if (threadIdx.x == 0) {
        float s = 0.0f;
#pragma unroll
        for (int i = 0; i < 8; i++) s += sp[i];
        g_part[blockIdx.x] = s;
    }
}

// ---------------------------------------------------------------------------
// K7: final reduce -> scalar loss. 1 block, 256 threads.
// ---------------------------------------------------------------------------
__global__ void __launch_bounds__(256) k7_final(float* __restrict__ out) {
    __shared__ float sh[256];
    const int t = threadIdx.x;
    float s = 0.0f;
    for (int i = t; i < K6_BLOCKS; i += 256) s += g_part[i];
    sh[t] = s;
    __syncthreads();
    for (int st = 128; st; st >>= 1) {
        if (t < st) sh[t] += sh[t + st];
        __syncthreads();
    }
    if (t == 0) out[0] = sh[0] / (float)HW_;   // RATIO == 1
}

extern "C" void kernel_launch(void* const* d_in, const int* in_sizes, int n_in,
                              void* d_out, int out_size) {
    const float* preds_S = (const float*)d_in[0];
    const float* preds_T = (const float*)d_in[1];
    const float* gt      = (const float*)d_in[2];
    float* out = (float*)d_out;

    k1_stats<<<dim3(K1_CHUNKS, N_), 256>>>(preds_T);
    k4_mask<<<N_, 256>>>(gt);
    k2_channel<<<N_, 256>>>();
    k3_spatial<<<N_, 256>>>();
    k5_roww<<<(N_ * HW_) / 256, 256>>>();
    k6_main<<<K6_BLOCKS, 256>>>(preds_S, preds_T);
    k7_final<<<1, 256>>>(out);
}